// round 12
// baseline (speedup 1.0000x reference)
#include <cuda_runtime.h>
#include <cuda_bf16.h>
#include <cstdint>

// Fixed problem shape
#define BB 8
#define NN 4096
#define EE 64
#define KK 32

#define DELTA_V 0.5f
#define DELTA_D 1.5f
#define GAMMA   0.001f

#define G1 256            // blocks per kernel
#define TPB 512
#define PTS 128           // points per block
#define SMEM_DYN (PTS * EE * 4)   // 32KB x stash

// Scratch ------------------------------------------------------------------
__device__ float    g_part[G1 * KK * EE];   // per-block centroid partial sums
__device__ float    g_pcnt[G1 * KK];        // per-block cluster counts
__device__ float    g_cent[BB * KK * EE];   // normalized centroids
__device__ int      g_lab[BB * NN];         // labels
__device__ float    g_acc[3];               // L_v, L_d, L_r (unnormalized)
__device__ unsigned g_bctr[BB];             // per-batch completion counters
__device__ unsigned g_bar = 0;              // finalize counter

__device__ __forceinline__ void cp_async16(void* smem_dst, const void* gmem_src) {
    uint32_t s = (uint32_t)__cvta_generic_to_shared(smem_dst);
    asm volatile("cp.async.cg.shared.global [%0], [%1], 16;" :: "r"(s), "l"(gmem_src));
}
__device__ __forceinline__ void cp_async_wait_all() {
    asm volatile("cp.async.commit_group;\ncp.async.wait_group 0;" ::: "memory");
}

// ===========================================================================
// K1: x->smem + labels + sort + bin sums; last block per batch reduces the
//     batch's 32 partial slices into normalized g_cent. Triggers PDL early.
// ===========================================================================
__global__ void __launch_bounds__(TPB) k_partial(const float* __restrict__ x,
                                                 const float* __restrict__ m) {
    extern __shared__ float sx[];             // [PTS*EE] x stash
    __shared__ int slab[PTS];
    __shared__ int ssorted[PTS];
    __shared__ int sbin[KK], soff[KK], scur[KK];
    __shared__ float scinv[KK];
    __shared__ unsigned lastflag;

    // Allow the dependent kernel to start launching immediately; it self-syncs.
    cudaTriggerProgrammaticLaunchCompletion();

    int tid = threadIdx.x, lane = tid & 31, warp = tid >> 5;
    int blk = blockIdx.x;
    int pbase = blk * PTS;
    int b = blk >> 5;                         // 32 blocks per batch

    if (tid < KK) sbin[tid] = 0;
    if (blk == 0 && tid < 3) g_acc[tid] = 0.0f;

    // ---- stream entire 32KB x tile via cp.async ---------------------------
    {
        const float4* x4 = (const float4*)(x + (size_t)pbase * EE);
        float4* sx4 = (float4*)sx;
        #pragma unroll
        for (int i = 0; i < 4; ++i)
            cp_async16(&sx4[tid + i * TPB], &x4[tid + i * TPB]);
    }

    // ---- both mask loads issued before any shuffle work -------------------
    {
        int p0 = warp * 4 + (lane >> 3);
        int p1 = 64 + p0;
        int k0 = (lane & 7) * 4;
        float4 mv0 = *(const float4*)(m + (size_t)(pbase + p0) * KK + k0);
        float4 mv1 = *(const float4*)(m + (size_t)(pbase + p1) * KK + k0);
        float s0 = mv0.x * k0 + mv0.y * (k0 + 1) + mv0.z * (k0 + 2) + mv0.w * (k0 + 3);
        float s1 = mv1.x * k0 + mv1.y * (k0 + 1) + mv1.z * (k0 + 2) + mv1.w * (k0 + 3);
        #pragma unroll
        for (int o = 1; o < 8; o <<= 1) {
            s0 += __shfl_xor_sync(0xffffffffu, s0, o);
            s1 += __shfl_xor_sync(0xffffffffu, s1, o);
        }
        if ((lane & 7) == 0) {
            slab[p0] = (int)(s0 + 0.5f);
            slab[p1] = (int)(s1 + 0.5f);
        }
    }
    __syncthreads();

    // ---- counting sort -----------------------------------------------------
    if (tid < PTS) atomicAdd(&sbin[slab[tid]], 1);
    __syncthreads();
    if (tid < KK) {
        int c = sbin[tid];
        int pref = c;
        #pragma unroll
        for (int o = 1; o < 32; o <<= 1) {
            int nv = __shfl_up_sync(0xffffffffu, pref, o);
            if (lane >= o) pref += nv;
        }
        soff[tid] = pref - c;
        scur[tid] = pref - c;
    }
    __syncthreads();
    if (tid < PTS) {
        int pos = atomicAdd(&scur[slab[tid]], 1);
        ssorted[pos] = tid;
        g_lab[pbase + tid] = slab[tid];       // persist labels for K3
    }
    cp_async_wait_all();
    __syncthreads();

    // ---- per-bin accumulation from SMEM (no atomics) ----------------------
    #pragma unroll
    for (int kb = 0; kb < 2; ++kb) {
        int k = warp * 2 + kb;
        int start = soff[k], cnt = sbin[k], end = start + cnt;
        float ax = 0.0f, ay = 0.0f;
        for (int base = start; base < end; base += 4) {
            float2 v0 = {0,0}, v1 = {0,0}, v2 = {0,0}, v3 = {0,0};
            v0 = *(const float2*)(sx + ssorted[base] * EE + lane * 2);
            if (base + 1 < end) v1 = *(const float2*)(sx + ssorted[base+1] * EE + lane * 2);
            if (base + 2 < end) v2 = *(const float2*)(sx + ssorted[base+2] * EE + lane * 2);
            if (base + 3 < end) v3 = *(const float2*)(sx + ssorted[base+3] * EE + lane * 2);
            ax += (v0.x + v1.x) + (v2.x + v3.x);
            ay += (v0.y + v1.y) + (v2.y + v3.y);
        }
        float2 acc = {ax, ay};
        *(float2*)(&g_part[(size_t)blk * (KK*EE) + k * EE + lane * 2]) = acc;
        if (lane == 0) g_pcnt[blk * KK + k] = (float)cnt;
    }

    // ---- last block of the batch reduces its 32 slices -> g_cent ----------
    __threadfence();
    __syncthreads();
    if (tid == 0) lastflag = atomicAdd(&g_bctr[b], 1u);
    __syncthreads();
    if (lastflag == 31) {
        if (tid < KK) {
            float c = 0.0f;
            #pragma unroll
            for (int j = 0; j < 32; ++j)
                c += __ldcg(&g_pcnt[((b << 5) | j) * KK + tid]);
            scinv[tid] = 1.0f / c;
        }
        __syncthreads();
        #pragma unroll
        for (int i = 0; i < 4; ++i) {
            int col = tid + i * TPB;          // 4 columns per thread
            float s0 = 0.0f, s1 = 0.0f, s2 = 0.0f, s3 = 0.0f;
            #pragma unroll
            for (int j = 0; j < 32; j += 4) {
                s0 += __ldcg(&g_part[(size_t)((b << 5) | (j    )) * (KK*EE) + col]);
                s1 += __ldcg(&g_part[(size_t)((b << 5) | (j + 1)) * (KK*EE) + col]);
                s2 += __ldcg(&g_part[(size_t)((b << 5) | (j + 2)) * (KK*EE) + col]);
                s3 += __ldcg(&g_part[(size_t)((b << 5) | (j + 3)) * (KK*EE) + col]);
            }
            g_cent[b * (KK*EE) + col] = ((s0 + s1) + (s2 + s3)) * scinv[col >> 6];
        }
        if (tid == 0) g_bctr[b] = 0;          // reset for next graph replay
    }
}

// ===========================================================================
// K3 (PDL secondary): prefetch x BEFORE the dependency sync, then loss terms.
// ===========================================================================
__global__ void __launch_bounds__(TPB) k_loss(const float* __restrict__ x,
                                              float* __restrict__ out) {
    extern __shared__ float sx[];             // [PTS*EE] x stash
    __shared__ float sc[KK * EE];
    __shared__ float ct[KK * EE];
    __shared__ int   slab[PTS];
    __shared__ float bsum;

    int tid = threadIdx.x, lane = tid & 31;
    int blk = blockIdx.x;
    int pbase = blk * PTS;
    int b = blk >> 5;

    // ---- x prefetch: no dependency on K1, runs concurrently with K1 -------
    {
        const float4* x4 = (const float4*)(x + (size_t)pbase * EE);
        float4* sx4 = (float4*)sx;
        #pragma unroll
        for (int i = 0; i < 4; ++i)
            cp_async16(&sx4[tid + i * TPB], &x4[tid + i * TPB]);
    }
    if (tid == 0) bsum = 0.0f;

    // ---- wait for K1's writes (g_cent, g_lab) to be visible ---------------
    cudaGridDependencySynchronize();

    ((float4*)sc)[tid] = __ldcg(((const float4*)(g_cent + b * (KK*EE))) + tid);
    if (tid < PTS) slab[tid] = g_lab[pbase + tid];
    cp_async_wait_all();
    __syncthreads();

    // ---- variance hinge: 16-lane group per point, 2-pt ILP, from SMEM -----
    {
        int gid = tid >> 4, gl = tid & 15;
        float lv = 0.0f;
        #pragma unroll
        for (int it = 0; it < 2; ++it) {
            int iA = it * 64 + gid;
            int iB = iA + 32;
            int labA = slab[iA], labB = slab[iB];
            float4 xA = ((const float4*)sx)[iA * 16 + gl];
            float4 xB = ((const float4*)sx)[iB * 16 + gl];
            float4 cA = ((const float4*)sc)[labA * 16 + gl];
            float4 cB = ((const float4*)sc)[labB * 16 + gl];
            float a0 = xA.x - cA.x, a1 = xA.y - cA.y, a2 = xA.z - cA.z, a3 = xA.w - cA.w;
            float b0 = xB.x - cB.x, b1 = xB.y - cB.y, b2 = xB.z - cB.z, b3 = xB.w - cB.w;
            float sqA = a0 * a0 + a1 * a1 + a2 * a2 + a3 * a3;
            float sqB = b0 * b0 + b1 * b1 + b2 * b2 + b3 * b3;
            #pragma unroll
            for (int o = 8; o; o >>= 1) {
                sqA += __shfl_xor_sync(0xffffffffu, sqA, o);
                sqB += __shfl_xor_sync(0xffffffffu, sqB, o);
            }
            if (gl == 0) {
                float hA = sqrtf(sqA) - DELTA_V;
                float hB = sqrtf(sqB) - DELTA_V;
                if (hA > 0.0f) lv += hA * hA;
                if (hB > 0.0f) lv += hB * hB;
            }
        }
        if (gl == 0) atomicAdd(&bsum, lv);
        __syncthreads();
        if (tid == 0) atomicAdd(&g_acc[0], bsum);
    }

    // ---- pairwise hinge + reg term (one block per batch) ------------------
    if ((blk & 31) == 0) {
        for (int i = tid; i < KK * EE; i += TPB) {
            int e = i >> 5, k = i & 31;
            ct[i] = sc[k * EE + e];            // transposed, lane-contiguous
        }
        __syncthreads();

        float ld = 0.0f, lr = 0.0f;
        #pragma unroll
        for (int rep = 0; rep < 2; ++rep) {
            int pr = rep * TPB + tid;
            int k1 = pr >> 5, k2 = pr & 31;
            float sq = 0.0f;
            if (k1 == k2) {
                #pragma unroll
                for (int e = 0; e < EE; e++) { float v = sc[k1 * EE + e]; sq += v * v; }
                lr += sqrtf(sq);
            } else {
                #pragma unroll
                for (int e = 0; e < EE; e++) {
                    float d = sc[k1 * EE + e] - ct[e * KK + k2];
                    sq += d * d;
                }
                float h = 2.0f * DELTA_D - sqrtf(sq);
                if (h > 0.0f) ld += h * h;
            }
        }
        #pragma unroll
        for (int o = 16; o; o >>= 1) {
            ld += __shfl_xor_sync(0xffffffffu, ld, o);
            lr += __shfl_xor_sync(0xffffffffu, lr, o);
        }
        if (lane == 0) {
            atomicAdd(&g_acc[1], ld);
            atomicAdd(&g_acc[2], lr);
        }
    }

    // ---- finalize: last arrival writes output -----------------------------
    __syncthreads();
    if (tid == 0) {
        __threadfence();
        unsigned r = atomicAdd(&g_bar, 1u);
        if (r == G1 - 1) {
            float Lv = *(volatile float*)&g_acc[0] / (float)(BB * NN);
            float Ld = *(volatile float*)&g_acc[1] / (float)(BB * KK * (KK - 1));
            float Lr = *(volatile float*)&g_acc[2] / (float)(BB * KK);
            out[0] = Lv + Ld + GAMMA * Lr;
            __threadfence();
            atomicExch(&g_bar, 0u);            // ready for next replay
        }
    }
}

// --------------------------------------------------------------------------
extern "C" void kernel_launch(void* const* d_in, const int* in_sizes, int n_in,
                              void* d_out, int out_size) {
    const float* x = (const float*)d_in[0];
    const float* m = (const float*)d_in[1];
    if (in_sizes[0] == BB * NN * KK && in_sizes[1] == BB * NN * EE) {
        x = (const float*)d_in[1];
        m = (const float*)d_in[0];
    }
    static bool attr_set = false;
    if (!attr_set) {
        cudaFuncSetAttribute(k_partial, cudaFuncAttributeMaxDynamicSharedMemorySize, SMEM_DYN);
        cudaFuncSetAttribute(k_loss,    cudaFuncAttributeMaxDynamicSharedMemorySize, SMEM_DYN);
        attr_set = true;
    }

    k_partial<<<G1, TPB, SMEM_DYN>>>(x, m);

    // K3 with Programmatic Dependent Launch: overlaps its x prefetch with K1.
    cudaLaunchConfig_t cfg = {};
    cfg.gridDim = dim3(G1);
    cfg.blockDim = dim3(TPB);
    cfg.dynamicSmemBytes = SMEM_DYN;
    cfg.stream = 0;
    cudaLaunchAttribute attr[1];
    attr[0].id = cudaLaunchAttributeProgrammaticStreamSerialization;
    attr[0].val.programmaticStreamSerializationAllowed = 1;
    cfg.attrs = attr;
    cfg.numAttrs = 1;
    cudaLaunchKernelEx(&cfg, k_loss, x, (float*)d_out);
}

// round 13
// speedup vs baseline: 1.1031x; 1.1031x over previous
#include <cuda_runtime.h>
#include <cuda_bf16.h>
#include <cstdint>

// Fixed problem shape
#define BB 8
#define NN 4096
#define EE 64
#define KK 32

#define DELTA_V 0.5f
#define DELTA_D 1.5f
#define GAMMA   0.001f

#define G1 256            // blocks per kernel
#define TPB 512
#define PTS 128           // points per block
#define SMEM_DYN (PTS * EE * 4)   // 32KB x stash

// Scratch ------------------------------------------------------------------
__device__ float    g_csum[BB * KK * EE];   // centroid sums (red.add target; re-zeroed by K3)
__device__ float    g_cnt[BB * KK];         // cluster counts (red.add target; re-zeroed by K3)
__device__ int      g_lab[BB * NN];         // labels
__device__ float    g_acc[3];               // L_v, L_d, L_r (unnormalized)
__device__ unsigned g_bar = 0;              // finalize counter

__device__ __forceinline__ void cp_async16(void* smem_dst, const void* gmem_src) {
    uint32_t s = (uint32_t)__cvta_generic_to_shared(smem_dst);
    asm volatile("cp.async.cg.shared.global [%0], [%1], 16;" :: "r"(s), "l"(gmem_src));
}
__device__ __forceinline__ void cp_async_wait_all() {
    asm volatile("cp.async.commit_group;\ncp.async.wait_group 0;" ::: "memory");
}
__device__ __forceinline__ void red_add_f32(float* p, float v) {
    asm volatile("red.global.add.f32 [%0], %1;" :: "l"(p), "f"(v) : "memory");
}

// ===========================================================================
// K1: x->smem (cp.async) + labels + sort + bin sums -> fire-and-forget
//     red.global.add into g_csum/g_cnt. No partial buffers, no reduce kernel.
// ===========================================================================
__global__ void __launch_bounds__(TPB) k_partial(const float* __restrict__ x,
                                                 const float* __restrict__ m) {
    extern __shared__ float sx[];             // [PTS*EE] x stash
    __shared__ int slab[PTS];
    __shared__ int ssorted[PTS];
    __shared__ int sbin[KK], soff[KK], scur[KK];

    int tid = threadIdx.x, lane = tid & 31, warp = tid >> 5;
    int blk = blockIdx.x;
    int pbase = blk * PTS;
    int b = blk >> 5;                         // 32 blocks per batch

    if (tid < KK) sbin[tid] = 0;
    if (blk == 0 && tid < 3) g_acc[tid] = 0.0f;

    // ---- stream entire 32KB x tile via cp.async ---------------------------
    {
        const float4* x4 = (const float4*)(x + (size_t)pbase * EE);
        float4* sx4 = (float4*)sx;
        #pragma unroll
        for (int i = 0; i < 4; ++i)
            cp_async16(&sx4[tid + i * TPB], &x4[tid + i * TPB]);
    }

    // ---- labels: both mask loads issued before shuffle work ---------------
    {
        int p0 = warp * 4 + (lane >> 3);
        int p1 = 64 + p0;
        int k0 = (lane & 7) * 4;
        float4 mv0 = *(const float4*)(m + (size_t)(pbase + p0) * KK + k0);
        float4 mv1 = *(const float4*)(m + (size_t)(pbase + p1) * KK + k0);
        float s0 = mv0.x * k0 + mv0.y * (k0 + 1) + mv0.z * (k0 + 2) + mv0.w * (k0 + 3);
        float s1 = mv1.x * k0 + mv1.y * (k0 + 1) + mv1.z * (k0 + 2) + mv1.w * (k0 + 3);
        #pragma unroll
        for (int o = 1; o < 8; o <<= 1) {
            s0 += __shfl_xor_sync(0xffffffffu, s0, o);
            s1 += __shfl_xor_sync(0xffffffffu, s1, o);
        }
        if ((lane & 7) == 0) {
            slab[p0] = (int)(s0 + 0.5f);
            slab[p1] = (int)(s1 + 0.5f);
        }
    }
    __syncthreads();

    // ---- counting sort -----------------------------------------------------
    if (tid < PTS) atomicAdd(&sbin[slab[tid]], 1);
    __syncthreads();
    if (tid < KK) {
        int c = sbin[tid];
        int pref = c;
        #pragma unroll
        for (int o = 1; o < 32; o <<= 1) {
            int nv = __shfl_up_sync(0xffffffffu, pref, o);
            if (lane >= o) pref += nv;
        }
        soff[tid] = pref - c;
        scur[tid] = pref - c;
    }
    __syncthreads();
    if (tid < PTS) {
        int pos = atomicAdd(&scur[slab[tid]], 1);
        ssorted[pos] = tid;
        g_lab[pbase + tid] = slab[tid];       // persist labels for K3
    }
    cp_async_wait_all();
    __syncthreads();

    // ---- per-bin accumulation, then fire-and-forget global reduction ------
    #pragma unroll
    for (int kb = 0; kb < 2; ++kb) {
        int k = warp * 2 + kb;
        int start = soff[k], cnt = sbin[k], end = start + cnt;
        if (cnt == 0) continue;               // nothing to contribute
        float ax = 0.0f, ay = 0.0f;
        for (int base = start; base < end; base += 4) {
            float2 v0 = {0,0}, v1 = {0,0}, v2 = {0,0}, v3 = {0,0};
            v0 = *(const float2*)(sx + ssorted[base] * EE + lane * 2);
            if (base + 1 < end) v1 = *(const float2*)(sx + ssorted[base+1] * EE + lane * 2);
            if (base + 2 < end) v2 = *(const float2*)(sx + ssorted[base+2] * EE + lane * 2);
            if (base + 3 < end) v3 = *(const float2*)(sx + ssorted[base+3] * EE + lane * 2);
            ax += (v0.x + v1.x) + (v2.x + v3.x);
            ay += (v0.y + v1.y) + (v2.y + v3.y);
        }
        float* dst = &g_csum[(b * KK + k) * EE + lane * 2];
        red_add_f32(dst,     ax);
        red_add_f32(dst + 1, ay);
        if (lane == 0) red_add_f32(&g_cnt[b * KK + k], (float)cnt);
    }
}

// ===========================================================================
// K3: centroid normalize + variance hinge + pairs/reg + finalize.
//     Last block zeroes g_csum/g_cnt for the next graph replay.
// ===========================================================================
__global__ void __launch_bounds__(TPB) k_loss(const float* __restrict__ x,
                                              float* __restrict__ out) {
    extern __shared__ float sx[];             // [PTS*EE] x stash
    __shared__ float sc[KK * EE];
    __shared__ float ct[KK * EE];
    __shared__ float sinv[KK];
    __shared__ int   slab[PTS];
    __shared__ float bsum;

    int tid = threadIdx.x, lane = tid & 31;
    int blk = blockIdx.x;
    int pbase = blk * PTS;
    int b = blk >> 5;

    // x tile via cp.async (L2-warm after K1)
    {
        const float4* x4 = (const float4*)(x + (size_t)pbase * EE);
        float4* sx4 = (float4*)sx;
        #pragma unroll
        for (int i = 0; i < 4; ++i)
            cp_async16(&sx4[tid + i * TPB], &x4[tid + i * TPB]);
    }
    if (tid == 0) bsum = 0.0f;
    if (tid < KK) sinv[tid] = 1.0f / __ldcg(&g_cnt[b * KK + tid]);
    if (tid < PTS) slab[tid] = g_lab[pbase + tid];
    __syncthreads();
    {   // normalized centroids into smem (float4 per thread, 512*4 = 2048)
        float4 s4 = __ldcg(((const float4*)(g_csum + b * (KK*EE))) + tid);
        float inv = sinv[tid >> 4];           // tid*4 / 64
        s4.x *= inv; s4.y *= inv; s4.z *= inv; s4.w *= inv;
        ((float4*)sc)[tid] = s4;
    }
    cp_async_wait_all();
    __syncthreads();

    // variance hinge: 16-lane group per point, 2-pt ILP, all from SMEM
    {
        int gid = tid >> 4, gl = tid & 15;
        float lv = 0.0f;
        #pragma unroll
        for (int it = 0; it < 2; ++it) {
            int iA = it * 64 + gid;
            int iB = iA + 32;
            int labA = slab[iA], labB = slab[iB];
            float4 xA = ((const float4*)sx)[iA * 16 + gl];
            float4 xB = ((const float4*)sx)[iB * 16 + gl];
            float4 cA = ((const float4*)sc)[labA * 16 + gl];
            float4 cB = ((const float4*)sc)[labB * 16 + gl];
            float a0 = xA.x - cA.x, a1 = xA.y - cA.y, a2 = xA.z - cA.z, a3 = xA.w - cA.w;
            float b0 = xB.x - cB.x, b1 = xB.y - cB.y, b2 = xB.z - cB.z, b3 = xB.w - cB.w;
            float sqA = a0 * a0 + a1 * a1 + a2 * a2 + a3 * a3;
            float sqB = b0 * b0 + b1 * b1 + b2 * b2 + b3 * b3;
            #pragma unroll
            for (int o = 8; o; o >>= 1) {
                sqA += __shfl_xor_sync(0xffffffffu, sqA, o);
                sqB += __shfl_xor_sync(0xffffffffu, sqB, o);
            }
            if (gl == 0) {
                float hA = sqrtf(sqA) - DELTA_V;
                float hB = sqrtf(sqB) - DELTA_V;
                if (hA > 0.0f) lv += hA * hA;
                if (hB > 0.0f) lv += hB * hB;
            }
        }
        if (gl == 0) atomicAdd(&bsum, lv);
        __syncthreads();
        if (tid == 0) atomicAdd(&g_acc[0], bsum);
    }

    // pairwise hinge + reg term (one block per batch)
    if ((blk & 31) == 0) {
        for (int i = tid; i < KK * EE; i += TPB) {
            int e = i >> 5, k = i & 31;
            ct[i] = sc[k * EE + e];            // transposed, lane-contiguous
        }
        __syncthreads();

        float ld = 0.0f, lr = 0.0f;
        #pragma unroll
        for (int rep = 0; rep < 2; ++rep) {
            int pr = rep * TPB + tid;
            int k1 = pr >> 5, k2 = pr & 31;
            float sq = 0.0f;
            if (k1 == k2) {
                #pragma unroll
                for (int e = 0; e < EE; e++) { float v = sc[k1 * EE + e]; sq += v * v; }
                lr += sqrtf(sq);
            } else {
                #pragma unroll
                for (int e = 0; e < EE; e++) {
                    float d = sc[k1 * EE + e] - ct[e * KK + k2];
                    sq += d * d;
                }
                float h = 2.0f * DELTA_D - sqrtf(sq);
                if (h > 0.0f) ld += h * h;
            }
        }
        #pragma unroll
        for (int o = 16; o; o >>= 1) {
            ld += __shfl_xor_sync(0xffffffffu, ld, o);
            lr += __shfl_xor_sync(0xffffffffu, lr, o);
        }
        if (lane == 0) {
            atomicAdd(&g_acc[1], ld);
            atomicAdd(&g_acc[2], lr);
        }
    }

    // finalize: last arrival writes output + re-zeroes reduction buffers
    __syncthreads();
    if (tid == 0) {
        __threadfence();
        unsigned r = atomicAdd(&g_bar, 1u);
        if (r == G1 - 1) {
            float Lv = *(volatile float*)&g_acc[0] / (float)(BB * NN);
            float Ld = *(volatile float*)&g_acc[1] / (float)(BB * KK * (KK - 1));
            float Lr = *(volatile float*)&g_acc[2] / (float)(BB * KK);
            out[0] = Lv + Ld + GAMMA * Lr;
            atomicExch(&g_bar, 0u);            // safe: all blocks already arrived
        }
    }
    // last block (detected by re-checking g_bar==0 won't work; instead every
    // block zeroes its own 64-float share — all reads of g_csum happened at
    // kernel start, and __syncthreads above orders this block's reads first).
    {
        // Each of 256 blocks zeroes 64 floats of g_csum (256*64 = 16384) and
        // one g_cnt entry. Safe: every block finished READING g_csum/g_cnt
        // (its own loads completed before its first __syncthreads), and other
        // blocks only read the slice belonging to THEIR batch... which may be
        // this slice. So zero only after ALL blocks passed their loads:
        // enforced by doing the zeroing in the NEXT kernel? No — instead rely
        // on the fact that every K3 block loads g_csum at kernel START, and
        // zeroing happens at kernel END. Any still-running block must have
        // already completed its start-of-kernel loads? NOT guaranteed (a late
        // block may not have started). So gate zeroing on the finalize counter:
    }
    __syncthreads();
    if (*(volatile unsigned*)&g_bar == 0u) { } // no-op; zeroing handled below
    // Gated zeroing: only the block that observed r == G1-1 (all arrived ⇒ all
    // blocks passed their start-of-kernel loads) zeroes everything.
    __shared__ int s_last;
    if (tid == 0) s_last = 0;
    __syncthreads();
    if (tid == 0) {
        // recompute: we stored nothing; use a second counter-free check via
        // shared flag set during finalize
    }
    __syncthreads();
    // NOTE: zeroing is performed by the finalizing block, recorded via bsum
    // reuse — see k_zero_tail below (launched as 3rd tiny kernel).
}

// Tiny tail kernel: zero reduction buffers for the next graph replay.
__global__ void k_zero_tail() {
    int i = blockIdx.x * blockDim.x + threadIdx.x;   // 64 * 256 = 16384
    g_csum[i] = 0.0f;
    if (i < BB * KK) g_cnt[i] = 0.0f;
}

// --------------------------------------------------------------------------
extern "C" void kernel_launch(void* const* d_in, const int* in_sizes, int n_in,
                              void* d_out, int out_size) {
    const float* x = (const float*)d_in[0];
    const float* m = (const float*)d_in[1];
    if (in_sizes[0] == BB * NN * KK && in_sizes[1] == BB * NN * EE) {
        x = (const float*)d_in[1];
        m = (const float*)d_in[0];
    }
    cudaFuncSetAttribute(k_partial, cudaFuncAttributeMaxDynamicSharedMemorySize, SMEM_DYN);
    cudaFuncSetAttribute(k_loss,    cudaFuncAttributeMaxDynamicSharedMemorySize, SMEM_DYN);
    k_partial<<<G1, TPB, SMEM_DYN>>>(x, m);
    k_loss<<<G1, TPB, SMEM_DYN>>>(x, (float*)d_out);
    k_zero_tail<<<BB * KK * EE / 256, 256>>>();   // tiny; prepares next replay
}